// round 12
// baseline (speedup 1.0000x reference)
#include <cuda_runtime.h>
#include <cuda_bf16.h>
#include <cstdint>
#include <math.h>

// Problem constants
#define B_   8
#define L_   2048
#define FIN  32
#define D    256
#define H_   8
#define DH   32
#define DFF  1024
#define S_   40
#define U_   40
#define NL   2

// ---------------- scratch (device globals; no allocation allowed) ----------------
__device__ float g_h  [B_*L_*D];
__device__ float g_q  [B_*L_*D];
__device__ float g_k  [B_*L_*D];
__device__ float g_v  [B_*L_*D];
__device__ float g_nx [B_*L_*D];
__device__ float g_M  [B_*H_*L_];
__device__ int   g_top[B_*H_*U_];
__device__ float g_vm [B_*H_*DH];
__device__ float g_ctxl[B_*H_*DH];
__device__ float g_base[B_*D];
__device__ float g_am[B_*H_*4*U_];
__device__ float g_al[B_*H_*4*U_];
__device__ float g_av[B_*H_*4*U_*DH];

// bf16 hi/lo planes (K-chunked layout: [K/32][rows][32] with in-chunk swizzle)
__device__ __nv_bfloat16 g_x_hi [B_*L_*FIN], g_x_lo [B_*L_*FIN];
__device__ __nv_bfloat16 g_h_hi [B_*L_*D],   g_h_lo [B_*L_*D];
__device__ __nv_bfloat16 g_ff_hi[B_*L_*DFF], g_ff_lo[B_*L_*DFF];
#define LYR_SZ   786432
#define WT_TOTAL (FIN*D + NL*LYR_SZ)
__device__ __nv_bfloat16 g_wt_hi[WT_TOTAL], g_wt_lo[WT_TOTAL];

// =========================== helpers ===============================================
__device__ __forceinline__ uint32_t smem_u32(const void* p) {
    uint32_t a;
    asm("{ .reg .u64 t; cvta.to.shared.u64 t, %1; cvt.u32.u64 %0, t; }" : "=r"(a) : "l"(p));
    return a;
}
__device__ __forceinline__ void split2(float x, float y, uint32_t& hi, uint32_t& lo) {
    __nv_bfloat162 h = __float22bfloat162_rn(make_float2(x, y));
    float2 hf = __bfloat1622float2(h);
    __nv_bfloat162 l = __float22bfloat162_rn(make_float2(x - hf.x, y - hf.y));
    hi = *(uint32_t*)&h; lo = *(uint32_t*)&l;
}
__device__ __forceinline__ void split_scalar(float v, __nv_bfloat16* hp, __nv_bfloat16* lp) {
    __nv_bfloat16 hb = __float2bfloat16(v);
    *hp = hb;
    *lp = __float2bfloat16(v - __bfloat162float(hb));
}

// chunked-plane index: element (row, k) in a tensor with Md rows
__device__ __forceinline__ size_t pidx(int row, int k, int Md) {
    int c = k >> 5, u = (k >> 3) & 3, e = k & 7;
    int u2 = u ^ ((row >> 1) & 3);
    return ((size_t)c * Md + row) * 32 + u2 * 8 + e;
}

#define MMA_BF16(c, a, b)                                                        \
    asm volatile("mma.sync.aligned.m16n8k16.row.col.f32.bf16.bf16.f32 "          \
        "{%0,%1,%2,%3}, {%4,%5,%6,%7}, {%8,%9}, {%0,%1,%2,%3};"                  \
        : "+f"((c)[0]), "+f"((c)[1]), "+f"((c)[2]), "+f"((c)[3])                  \
        : "r"((a)[0]), "r"((a)[1]), "r"((a)[2]), "r"((a)[3]),                     \
          "r"((b)[0]), "r"((b)[1]))

#define LDM4(r, addr)                                                            \
    asm volatile("ldmatrix.sync.aligned.m8n8.x4.shared.b16 {%0,%1,%2,%3}, [%4];" \
        : "=r"((r)[0]), "=r"((r)[1]), "=r"((r)[2]), "=r"((r)[3]) : "r"(addr))

#define MBAR_INIT(mb, n)  asm volatile("mbarrier.init.shared.b64 [%0], %1;" :: "r"(mb), "r"(n) : "memory")
#define MBAR_EXPECT(mb, tx) asm volatile("mbarrier.arrive.expect_tx.shared.b64 _, [%0], %1;" :: "r"(mb), "r"(tx) : "memory")
#define MBAR_WAIT(mb, ph) do {                                                          \
    asm volatile("{ .reg .pred P;\n\t"                                                  \
        "W_%=: mbarrier.try_wait.parity.acquire.cta.shared::cta.b64 P, [%0], %1, 0x989680;\n\t" \
        "@P bra.uni DN_%=; bra.uni W_%=; DN_%=: }"                                      \
        :: "r"(mb), "r"(ph) : "memory");                                                \
} while (0)
#define BULK_LD(dst, src, bytes, mb)                                                    \
    asm volatile("cp.async.bulk.shared::cluster.global.mbarrier::complete_tx::bytes "   \
        "[%0], [%1], %2, [%3];" :: "r"(dst), "l"(src), "r"(bytes), "r"(mb) : "memory")

// ======= 3-stage pipelined bf16x3 GEMM: bulk-copy loads, chunked operand planes ====
#define STAGE_B 32768
#define GEMM_SMEM_V4 (1024 + 3*STAGE_B)

__global__ __launch_bounds__(256, 2)
void mma_gemm_bf16(const __nv_bfloat16* __restrict__ Ahi, const __nv_bfloat16* __restrict__ Alo,
                   const __nv_bfloat16* __restrict__ Bhi, const __nv_bfloat16* __restrict__ Blo,
                   const float* __restrict__ b0, const float* __restrict__ b1,
                   const float* __restrict__ b2,
                   float* __restrict__ C0, float* __restrict__ C1, float* __restrict__ C2,
                   __nv_bfloat16* __restrict__ Chi, __nv_bfloat16* __restrict__ Clo,
                   const float* __restrict__ Radd,
                   int M, int N, int K, int relu, int mode, int split3)
{
    extern __shared__ uint32_t sm[];
    int tid  = threadIdx.x;
    int brow = blockIdx.y * 128;
    int bcol = blockIdx.x * 128;
    int w = tid >> 5, lane = tid & 31;
    int gid = lane >> 2, tig = lane & 3;
    int moff = (w >> 1) * 32, noff = (w & 1) * 64;
    uint32_t smb = smem_u32(sm);
    uint32_t stg = smb + 1024;

    if (tid == 0) {
        MBAR_INIT(smb,      1);
        MBAR_INIT(smb + 8,  1);
        MBAR_INIT(smb + 16, 1);
    }
    __syncthreads();

    int mat = lane >> 3, r8 = lane & 7;
    uint32_t aoffk[2][2], boffk[4][2];
    #pragma unroll
    for (int mt = 0; mt < 2; mt++) {
        int row = moff + mt * 16 + (mat & 1) * 8 + r8;
        int sw = (row >> 1) & 3;
        #pragma unroll
        for (int ks = 0; ks < 2; ks++) {
            int u = ks * 2 + (mat >> 1);
            aoffk[mt][ks] = (uint32_t)(row * 64 + ((u ^ sw) << 4));
        }
    }
    #pragma unroll
    for (int p = 0; p < 4; p++) {
        int row = noff + p * 16 + (mat >> 1) * 8 + r8;
        int sw = (row >> 1) & 3;
        #pragma unroll
        for (int ks = 0; ks < 2; ks++) {
            int u = ks * 2 + (mat & 1);
            boffk[p][ks] = (uint32_t)(row * 64 + ((u ^ sw) << 4));
        }
    }

    const int NC = K >> 5;

    auto issue = [&](int c) {
        int s = c % 3;
        uint32_t sb = stg + (uint32_t)s * STAGE_B;
        uint32_t mb = smb + (uint32_t)s * 8;
        MBAR_EXPECT(mb, 32768u);
        const __nv_bfloat16* a0 = Ahi + ((size_t)c * M + brow) * 32;
        const __nv_bfloat16* a1 = Alo + ((size_t)c * M + brow) * 32;
        const __nv_bfloat16* b0p = Bhi + ((size_t)c * N + bcol) * 32;
        const __nv_bfloat16* b1p = Blo + ((size_t)c * N + bcol) * 32;
        BULK_LD(sb,          a0,  8192u, mb);
        BULK_LD(sb + 8192,   a1,  8192u, mb);
        BULK_LD(sb + 16384,  b0p, 8192u, mb);
        BULK_LD(sb + 24576,  b1p, 8192u, mb);
    };

    if (tid == 0) {
        issue(0);
        if (NC > 1) issue(1);
    }

    float acc[2][8][4] = {};

    for (int c = 0; c < NC; c++) {
        __syncthreads();
        if (tid == 0 && c + 2 < NC) issue(c + 2);
        MBAR_WAIT(smb + (uint32_t)(c % 3) * 8, (c / 3) & 1);

        uint32_t bb = stg + (uint32_t)(c % 3) * STAGE_B;
        uint32_t Ahb = bb, Alb = bb + 8192, Bhb = bb + 16384, Blb = bb + 24576;

        #pragma unroll
        for (int ks = 0; ks < 2; ks++) {
            uint32_t afh[2][4], afl[2][4];
            #pragma unroll
            for (int mt = 0; mt < 2; mt++) {
                LDM4(afh[mt], Ahb + aoffk[mt][ks]);
                LDM4(afl[mt], Alb + aoffk[mt][ks]);
            }
            #pragma unroll
            for (int p = 0; p < 4; p++) {
                uint32_t bfh[4], bfl[4];
                LDM4(bfh, Bhb + boffk[p][ks]);
                LDM4(bfl, Blb + boffk[p][ks]);
                #pragma unroll
                for (int mt = 0; mt < 2; mt++)
                    #pragma unroll
                    for (int hf = 0; hf < 2; hf++) {
                        int nt = p * 2 + hf;
                        MMA_BF16(acc[mt][nt], afh[mt], &bfh[hf * 2]);
                        MMA_BF16(acc[mt][nt], afh[mt], &bfl[hf * 2]);
                        MMA_BF16(acc[mt][nt], afl[mt], &bfh[hf * 2]);
                    }
            }
        }
    }

    float* Cf; const float* bp_; int cb, Nst;
    if (split3) {
        int mi = bcol >> 8;
        Cf  = (mi == 0) ? C0 : (mi == 1 ? C1 : C2);
        bp_ = (mi == 0) ? b0 : (mi == 1 ? b1 : b2);
        cb = bcol & 255; Nst = 256;
    } else {
        Cf = C0; bp_ = b0; cb = bcol; Nst = N;
    }

    #pragma unroll
    for (int mt = 0; mt < 2; mt++) {
        int r0 = brow + moff + mt * 16 + gid;
        #pragma unroll
        for (int nt = 0; nt < 8; nt++) {
            int c = cb + noff + nt * 8 + tig * 2;
            float bb0 = bp_[c], bb1 = bp_[c + 1];
            float2 o0 = make_float2(acc[mt][nt][0] + bb0, acc[mt][nt][1] + bb1);
            float2 o1 = make_float2(acc[mt][nt][2] + bb0, acc[mt][nt][3] + bb1);
            size_t i0 = (size_t)r0 * Nst + c;
            size_t i1 = (size_t)(r0 + 8) * Nst + c;
            if (Radd) {
                float2 ra0 = *(const float2*)(Radd + i0);
                float2 ra1 = *(const float2*)(Radd + i1);
                o0.x += ra0.x; o0.y += ra0.y;
                o1.x += ra1.x; o1.y += ra1.y;
            }
            if (relu) {
                o0.x = fmaxf(o0.x, 0.f); o0.y = fmaxf(o0.y, 0.f);
                o1.x = fmaxf(o1.x, 0.f); o1.y = fmaxf(o1.y, 0.f);
            }
            if (mode & 1) {
                *(float2*)(Cf + i0) = o0;
                *(float2*)(Cf + i1) = o1;
            }
            if (mode & 2) {
                uint32_t h0, l0, h1, l1;
                split2(o0.x, o0.y, h0, l0);
                split2(o1.x, o1.y, h1, l1);
                size_t p0 = pidx(r0,     c, 16384);
                size_t p1 = pidx(r0 + 8, c, 16384);
                *(uint32_t*)(Chi + p0) = h0; *(uint32_t*)(Clo + p0) = l0;
                *(uint32_t*)(Chi + p1) = h1; *(uint32_t*)(Clo + p1) = l1;
            }
        }
    }
}

// ---------------- batched transpose+split of ALL weights (chunked layout) ----------
__global__ void transpose_all_kernel(const float* __restrict__ w_in,
                                     const float* __restrict__ wq, const float* __restrict__ wk,
                                     const float* __restrict__ wv, const float* __restrict__ wo,
                                     const float* __restrict__ f1, const float* __restrict__ f2,
                                     __nv_bfloat16* __restrict__ hi, __nv_bfloat16* __restrict__ lo)
{
    const int start[14] = {0, 8, 72, 136, 200, 264, 520, 776, 840, 904, 968, 1032, 1288, 1544};
    int t = blockIdx.x;
    int m = 0;
    #pragma unroll
    for (int i = 1; i < 14; i++) if (t >= start[i]) m = i;
    int layer = (m >= 7) ? 1 : 0;
    int mi = (m == 0) ? 0 : ((m - 1) % 6) + 1;
    const float* src; int K, N, Nchunk, nofs; size_t dst;
    size_t base = (size_t)FIN * D + (size_t)layer * LYR_SZ;
    switch (mi) {
        case 0: src = w_in;                          K = FIN; N = D;   Nchunk = 256;  nofs = 0;   dst = 0;             break;
        case 1: src = wq + (size_t)layer * D * D;    K = D;   N = D;   Nchunk = 768;  nofs = 0;   dst = base;          break;
        case 2: src = wk + (size_t)layer * D * D;    K = D;   N = D;   Nchunk = 768;  nofs = 256; dst = base;          break;
        case 3: src = wv + (size_t)layer * D * D;    K = D;   N = D;   Nchunk = 768;  nofs = 512; dst = base;          break;
        case 4: src = wo + (size_t)layer * D * D;    K = D;   N = D;   Nchunk = 256;  nofs = 0;   dst = base + 196608; break;
        case 5: src = f1 + (size_t)layer * D * DFF;  K = D;   N = DFF; Nchunk = 1024; nofs = 0;   dst = base + 262144; break;
        default:src = f2 + (size_t)layer * DFF * D;  K = DFF; N = D;   Nchunk = 256;  nofs = 0;   dst = base + 524288; break;
    }
    int lt = t - start[m];
    int ntn = N >> 5;
    int nb = (lt % ntn) << 5, kb = (lt / ntn) << 5;

    __shared__ float tbuf[32][33];
    int tx = threadIdx.x, ty = threadIdx.y;
    #pragma unroll
    for (int i = ty; i < 32; i += 8)
        tbuf[i][tx] = src[(size_t)(kb + i) * N + nb + tx];
    __syncthreads();
    #pragma unroll
    for (int i = ty; i < 32; i += 8) {
        float v = tbuf[tx][i];
        size_t o = dst + pidx(nofs + nb + i, kb + tx, Nchunk);
        split_scalar(v, hi + o, lo + o);
    }
}

// ---------------- plain split ------------------------------------------------------
__global__ void split_kernel(const float* __restrict__ in,
                             __nv_bfloat16* __restrict__ hi,
                             __nv_bfloat16* __restrict__ lo, int n)
{
    int i = (blockIdx.x * blockDim.x + threadIdx.x) * 2;
    if (i >= n) return;
    float2 v = *(const float2*)(in + i);
    uint32_t h, l;
    split2(v.x, v.y, h, l);
    size_t o = pidx(i >> 5, i & 31, 16384);
    *(uint32_t*)(hi + o) = h;
    *(uint32_t*)(lo + o) = l;
}

// -------- fused sampled-QK M-score + v-mean ----------------------------------------
#define QK_BLOCKS (B_*H_*L_/8)
__global__ void qkvm_kernel(const float* __restrict__ q, const float* __restrict__ k,
                            const int* __restrict__ idx, float* __restrict__ Mout,
                            const float* __restrict__ v, float* __restrict__ vm)
{
    if (blockIdx.x < QK_BLOCKS) {
        int gw   = (blockIdx.x * blockDim.x + threadIdx.x) >> 5;
        int lane = threadIdx.x & 31;
        int l  = gw & (L_ - 1);
        int bh = gw >> 11;
        int b  = bh >> 3, h = bh & 7;

        int g  = lane >> 3;
        int d4 = (lane & 7) << 2;
        float4 q4 = *(const float4*)(q + ((size_t)b * L_ + l) * D + h * DH + d4);
        const float* kbase = k + (size_t)b * L_ * D + h * DH;
        const int*   irow  = idx + l * S_;

        float mx = -1e30f, sm = 0.0f;
        #pragma unroll 5
        for (int s0 = 0; s0 < S_; s0 += 4) {
            int ki = __ldg(&irow[s0 + g]);
            float4 kv = *(const float4*)(kbase + (size_t)ki * D + d4);
            float p = q4.x * kv.x + q4.y * kv.y + q4.z * kv.z + q4.w * kv.w;
            p += __shfl_xor_sync(0xffffffffu, p, 1);
            p += __shfl_xor_sync(0xffffffffu, p, 2);
            p += __shfl_xor_sync(0xffffffffu, p, 4);
            mx = fmaxf(mx, p);
            sm += p;
        }
        mx = fmaxf(mx, __shfl_xor_sync(0xffffffffu, mx, 8));
        mx = fmaxf(mx, __shfl_xor_sync(0xffffffffu, mx, 16));
        sm += __shfl_xor_sync(0xffffffffu, sm, 8);
        sm += __shfl_xor_sync(0xffffffffu, sm, 16);
        if (lane == 0) Mout[gw] = mx - sm * (1.0f / (float)L_);
    } else {
        int bh = blockIdx.x - QK_BLOCKS; int b = bh >> 3, h = bh & 7;
        int tid = threadIdx.x;
        int d = tid & 31, seg = tid >> 5;
        const float* vb = v + (size_t)b * L_ * D + h * DH + d;
        float acc = 0.0f;
        for (int l = seg; l < L_; l += 8) acc += vb[(size_t)l * D];
        __shared__ float sp[8][32];
        sp[seg][d] = acc;
        __syncthreads();
        if (tid < 32) {
            float s = 0.0f;
            #pragma unroll
            for (int i = 0; i < 8; i++) s += sp[i][tid];
            vm[bh * DH + tid] = s * (1.0f / (float)L_);
        }
    }
}

// ---------------- top-40 per (b,h) -------------------------------------------------
__global__ void topk_kernel(const float* __restrict__ Mv, int* __restrict__ top)
{
    int bh  = blockIdx.x;
    int tid = threadIdx.x;
    int w = tid >> 5, lane = tid & 31;
    __shared__ float sv[L_];
    __shared__ float wv_[8];
    __shared__ int   wi_[8];
    for (int i = tid; i < L_; i += 256) sv[i] = Mv[(size_t)bh * L_ + i];
    __syncthreads();

    for (int r = 0; r < U_; r++) {
        float bv = -1e30f; int bi = 0x7fffffff;
        #pragma unroll
        for (int j = 0; j < 8; j++) {
            int i = tid + j * 256;
            float v = sv[i];
            if (v > bv || (v == bv && i < bi)) { bv = v; bi = i; }
        }
        #pragma unroll
        for (int o = 16; o; o >>= 1) {
            float ov = __shfl_xor_sync(0xffffffffu, bv, o);
            int   oi = __shfl_xor_sync(0xffffffffu, bi, o);
            if (ov > bv || (ov == bv && oi < bi)) { bv = ov; bi = oi; }
        }
        if (lane == 0) { wv_[w] = bv; wi_[w] = bi; }
        __syncthreads();
        if (tid == 0) {
            float fv = wv_[0]; int fi = wi_[0];
            #pragma unroll
            for (int j = 1; j < 8; j++) {
                float ov = wv_[j]; int oi = wi_[j];
                if (ov > fv || (ov == fv && oi < fi)) { fv = ov; fi = oi; }
            }
            top[bh * U_ + r] = fi;
            sv[fi] = -1e30f;
        }
        __syncthreads();
    }
}

// --------- split-KV flash attention part: 4 splits of 512 keys per (b,h) ----------
__global__ __launch_bounds__(256, 1)
void attn_part_kernel(const float* __restrict__ q, const float* __restrict__ k,
                      const float* __restrict__ v, const int* __restrict__ top,
                      float* __restrict__ am, float* __restrict__ al,
                      float* __restrict__ av)
{
    __shared__ float Ks[128][33];
    __shared__ float Vs[128][33];
    __shared__ float qs[40][32];
    __shared__ float ps[8][128];
    __shared__ int   stop[40];

    int blk = blockIdx.x;
    int sp = blk & 3, bh = blk >> 2;
    int b = bh >> 3, h = bh & 7;
    int tid = threadIdx.x, w = tid >> 5, lane = tid & 31;

    if (tid < 40) stop[tid] = top[bh * U_ + tid];
    __syncthreads();
    for (int i = tid; i < 40 * 32; i += 256) {
        int u = i >> 5, d = i & 31;
        qs[u][d] = q[((size_t)b * L_ + stop[u]) * D + h * DH + d];
    }

    float m[5], l[5], acc[5];
    #pragma unroll
    for (int j = 0; j < 5; j++) { m[j] = -1e30f; l[j] = 0.f; acc[j] = 0.f; }
    const float scale = 0.1767766952966369f;
    const float* kb = k + (size_t)b * L_ * D + h * DH;
    const float* vb = v + (size_t)b * L_ * D + h * DH;
    __syncthreads();

    int tstart = sp * 512;
    for (int t0 = tstart; t0 < tstart + 512; t0 += 128) {
        for (int i = tid; i < 128 * 32; i += 256) {
            int r = i >> 5, d = i & 31;
            Ks[r][d] = kb[(size_t)(t0 + r) * D + d];
            Vs[r][d] = vb[(size_t)(t0 + r) * D + d];
        }
        __syncthreads();

        float sj[5][4];
        #pragma unroll
        for (int j = 0; j < 5; j++)
            #pragma unroll
            for (int i = 0; i < 4; i++) sj[j][i] = 0.f;
        #pragma unroll
        for (int d = 0; d < 32; d++) {
            float k0v = Ks[lane][d], k1v = Ks[lane + 32][d];
            float k2v = Ks[lane + 64][d], k3v = Ks[lane + 96][d];
            #pragma unroll
            for (int j = 0; j < 5; j++) {
                float qd = qs[w * 5 + j][d];
                sj[j][0] = fmaf(qd, k0v, sj[j][0]);
                sj[j][1] = fmaf(qd, k1v, sj[j][1]);
                sj[j][2] = fmaf(qd, k2v, sj[j][2]);
                sj[j][3] = fmaf(qd, k3v, sj[j][3]);
            }
        }
        #pragma unroll
        for (int j = 0; j < 5; j++) {
            float s0 = sj[j][0] * scale, s1 = sj[j][1] * scale;
            float s2 = sj[j][2] * scale, s3 = sj[j][3] * scale;
            float tm = fmaxf(fmaxf(s0, s1), fmaxf(s2, s3));
            #pragma unroll
            for (int o = 16; o; o >>= 1) tm = fmaxf(tm, __shfl_xor_sync(0xffffffffu, tm, o));
            float mn   = fmaxf(m[j], tm);
            float corr = __expf(m[j] - mn);
            float p0 = __expf(s0 - mn), p1 = __expf(s1 - mn);
            float p2 = __expf(s2 - mn), p3 = __expf(s3 - mn);
            float psum = p0 + p1 + p2 + p3;
            #pragma unroll
            for (int o = 16; o; o >>= 1) psum += __shfl_xor_sync(0xffffffffu, psum, o);
            l[j] = l[j] * corr + psum;
            m[j] = mn;
            ps[w][lane] = p0; ps[w][lane + 32] = p1; ps[w][lane + 64] = p2; ps[w][lane + 96] = p3;
            __syncwarp();
            float aa = acc[j] * corr;
            const float4* pv4 = (const float4*)ps[w];
            #pragma unroll 8
            for (int kk4 = 0; kk4 < 32; kk4++) {
                float4 p4 = pv4[kk4];
                int kk = kk4 * 4;
                aa = fmaf(p4.x, Vs[kk][lane],     aa);
                aa = fmaf(p4.y, Vs[kk + 1][lane], aa);
                aa = fmaf(p4.z, Vs[kk + 2][lane], aa);
                aa = fmaf(p4.w, Vs[kk + 3][lane], aa);
            }
            acc[j] = aa;
            __syncwarp();
        }
        __syncthreads();
    }
    #pragma unroll
    for (int j = 0; j < 5; j++) {
        int u = w * 5 + j;
        int pidx_ = (bh * 4 + sp) * U_ + u;
        if (lane == 0) { am[pidx_] = m[j]; al[pidx_] = l[j]; }
        av[(size_t)pidx_ * DH + lane] = acc[j];
    }
}

// --------- base = concat_h(vmean) @ wo + bo : one block per b ------------------------
__global__ void base_kernel(const float* __restrict__ vm, const float* __restrict__ wo0,
                            const float* __restrict__ bo0, float* __restrict__ base)
{
    int b = blockIdx.x;
    int c = threadIdx.x;
    const float* vmb = vm + b * D;
    float acc = bo0[c];
    for (int dd = 0; dd < D; dd++) acc = fmaf(vmb[dd], wo0[(size_t)dd * D + c], acc);
    base[b * D + c] = acc;
}

// --------- nx = h + base (broadcast per batch) ---------------------------------------
__global__ void basefill_kernel(const float* __restrict__ h, const float* __restrict__ base,
                                float* __restrict__ nx)
{
    int i2 = (blockIdx.x * blockDim.x + threadIdx.x) * 2;
    if (i2 >= B_ * L_ * D) return;
    int b = i2 >> 19;                 // / (L*D)
    int c = i2 & (D - 1);
    float2 hv = *(const float2*)(h + i2);
    float2 bv = *(const float2*)(base + b * D + c);
    float2 o = make_float2(hv.x + bv.x, hv.y + bv.y);
    *(float2*)(nx + i2) = o;
}

// --------- combine split-KV partials + correction: nx[top] += (o - vmean)@wo_h ------
__global__ __launch_bounds__(256, 2)
void corr_kernel(const int* __restrict__ top,
                 const float* __restrict__ am, const float* __restrict__ al,
                 const float* __restrict__ av, const float* __restrict__ vm,
                 const float* __restrict__ wo0, float* __restrict__ nx)
{
    int bh = blockIdx.x; int b = bh >> 3, h = bh & 7;
    int tid = threadIdx.x, w = tid >> 5, lane = tid & 31;
    __shared__ float od[40][33];
    __shared__ int stop[40];
    if (tid < 40) stop[tid] = top[bh * U_ + tid];
    __syncthreads();

    #pragma unroll
    for (int j = 0; j < 5; j++) {
        int u = w * 5 + j;
        int base = bh * 4 * U_ + u;
        float m0 = am[base], m1 = am[base + U_], m2 = am[base + 2*U_], m3 = am[base + 3*U_];
        float ms = fmaxf(fmaxf(m0, m1), fmaxf(m2, m3));
        float e0 = __expf(m0 - ms), e1 = __expf(m1 - ms);
        float e2 = __expf(m2 - ms), e3 = __expf(m3 - ms);
        float Lsum = al[base] * e0 + al[base + U_] * e1 + al[base + 2*U_] * e2 + al[base + 3*U_] * e3;
        float num = av[(size_t)base * DH + lane] * e0
                  + av[(size_t)(base + U_) * DH + lane] * e1
                  + av[(size_t)(base + 2*U_) * DH + lane] * e2
                  + av[(size_t)(base + 3*U_) * DH + lane] * e3;
        od[u][lane] = num / Lsum - vm[bh * DH + lane];
    }
    __syncthreads();

    // each thread owns column c; accumulate corrections for all 40 rows
    int c = tid;
    const float* woh = wo0 + (size_t)(h * DH) * D + c;
    for (int u = 0; u < U_; u++) {
        float val = 0.f;
        #pragma unroll
        for (int d = 0; d < DH; d++)
            val = fmaf(od[u][d], woh[(size_t)d * D], val);
        atomicAdd(nx + ((size_t)b * L_ + stop[u]) * D + c, val);
    }
}

// ---------- LayerNorm of pre-summed input + split (chunked plane writes) -----------
__global__ void add_ln_kernel(const float* __restrict__ sum,
                              const float* __restrict__ g, const float* __restrict__ bb,
                              float* __restrict__ hout,
                              __nv_bfloat16* __restrict__ hhi, __nv_bfloat16* __restrict__ hlo)
{
    int tid = threadIdx.x;
    int rl  = tid >> 7;
    int ct  = tid & 127;
    int row = blockIdx.x * 2 + rl;
    size_t off = (size_t)row * D + ct * 2;
    float2 v = *(const float2*)(sum + off);
    float s1 = v.x + v.y, s2 = v.x * v.x + v.y * v.y;
    #pragma unroll
    for (int o = 16; o; o >>= 1) {
        s1 += __shfl_xor_sync(0xffffffffu, s1, o);
        s2 += __shfl_xor_sync(0xffffffffu, s2, o);
    }
    __shared__ float a1[2][4], a2[2][4], mu[2], rv[2];
    int wr = (tid >> 5) & 3;
    int lane = tid & 31;
    if (lane == 0) { a1[rl][wr] = s1; a2[rl][wr] = s2; }
    __syncthreads();
    if (ct == 0) {
        float t1 = a1[rl][0] + a1[rl][1] + a1[rl][2] + a1[rl][3];
        float t2 = a2[rl][0] + a2[rl][1] + a2[rl][2] + a2[rl][3];
        float m = t1 * (1.0f / (float)D);
        float var = t2 * (1.0f / (float)D) - m * m;
        mu[rl] = m;
        rv[rl] = rsqrtf(var + 1e-5f);
    }
    __syncthreads();
    float m = mu[rl], r = rv[rl];
    float2 gg = *(const float2*)(g + ct * 2);
    float2 b2 = *(const float2*)(bb + ct * 2);
    float2 o;
    o.x = (v.x - m) * r * gg.x + b2.x;
    o.y = (v.y - m) * r * gg.y + b2.y;
    *(float2*)(hout + off) = o;
    uint32_t hi32, lo32;
    split2(o.x, o.y, hi32, lo32);
    size_t po = pidx(row, ct * 2, 16384);
    *(uint32_t*)(hhi + po) = hi32;
    *(uint32_t*)(hlo + po) = lo32;
}

// --------- last-layer attention for row L-1 only ------------------------------------
__global__ __launch_bounds__(256, 1)
void last_attn_kernel(const float* __restrict__ q, const float* __restrict__ k,
                      const float* __restrict__ v, const int* __restrict__ top,
                      const float* __restrict__ vm, float* __restrict__ ctxl)
{
    int bh = blockIdx.x; int b = bh >> 3, h = bh & 7;
    int tid = threadIdx.x;
    __shared__ int memb;
    __shared__ float qs[DH];
    __shared__ float sc[L_];
    __shared__ float red[256];
    __shared__ float part[8][DH];

    if (tid == 0) memb = 0;
    __syncthreads();
    if (tid < U_ && top[bh * U_ + tid] == (L_ - 1)) memb = 1;
    __syncthreads();
    if (!memb) {
        if (tid < DH) ctxl[bh * DH + tid] = vm[bh * DH + tid];
        return;
    }

    if (tid < DH) qs[tid] = q[((size_t)b * L_ + (L_ - 1)) * D + h * DH + tid];
    __syncthreads();

    const float* kb = k + (size_t)b * L_ * D + h * DH;
    const float scale = 0.1767766952966369f;
    float lmax = -1e30f;
    for (int l = tid; l < L_; l += 256) {
        const float4* kr = (const float4*)(kb + (size_t)l * D);
        float dot = 0.0f;
        #pragma unroll
        for (int j = 0; j < 8; j++) {
            float4 kv = __ldg(&kr[j]);
            dot += qs[4*j+0]*kv.x + qs[4*j+1]*kv.y + qs[4*j+2]*kv.z + qs[4*j+3]*kv.w;
        }
        dot *= scale;
        sc[l] = dot;
        lmax = fmaxf(lmax, dot);
    }
    red[tid] = lmax; __syncthreads();
    for (int s = 128; s; s >>= 1) { if (tid < s) red[tid] = fmaxf(red[tid], red[tid + s]); __syncthreads(); }
    float gmax = red[0];
    __syncthreads();
    float lsum = 0.0f;
    for (int l = tid; l < L_; l += 256) {
        float e = __expf(sc[l] - gmax);
        sc[l] = e;
        lsum += e;
    }
    red[tid] = lsum; __syncthreads();
    for (int s = 128; s; s >>= 1) { if (tid < s) red[tid] += red[tid + s]; __syncthreads(); }
    float inv = 1.0f / red[0];
    __syncthreads();

    int d = tid & 31, seg = tid >> 5;
    const float* vb = v + (size_t)b * L_ * D + h * DH + d;
    float acc = 0.0f;
    for (int l = seg; l < L_; l += 8) acc += sc[l] * vb[(size_t)l * D];
    part[seg][d] = acc;
    __syncthreads();
    if (tid < DH) {
        float s = 0.0f;
        #pragma unroll
        for (int i = 0; i < 8; i++) s += part[i][tid];
        ctxl[bh * DH + tid] = s * inv;
    }
}

// --------- final chain for row L-1 ---------------------------------------------------
__global__ __launch_bounds__(256, 1)
void final_head_kernel(const float* __restrict__ h, const float* __restrict__ ctxl,
                       const float* __restrict__ wo2, const float* __restrict__ bo2,
                       const float* __restrict__ ln1g, const float* __restrict__ ln1b,
                       const float* __restrict__ ff1, const float* __restrict__ bf1,
                       const float* __restrict__ ff2, const float* __restrict__ bf2,
                       const float* __restrict__ ln2g, const float* __restrict__ ln2b,
                       const float* __restrict__ w1, const float* __restrict__ b1,
                       const float* __restrict__ w2, const float* __restrict__ b2,
                       float* __restrict__ out)
{
    int b = blockIdx.x;
    int tid = threadIdx.x;
    int w = tid >> 5, lane = tid & 31;
    __shared__ float row[D], ctxr[D], hb1[D], yb[DFF], hb2[D];
    __shared__ float a1[8], a2[8], stat[2];

    row[tid]  = h[((size_t)b * L_ + (L_ - 1)) * D + tid];
    ctxr[tid] = ctxl[b * D + tid];
    __syncthreads();

    float acc = bo2[tid];
    for (int dd = 0; dd < D; dd++) acc = fmaf(ctxr[dd], wo2[dd * D + tid], acc);
    float val = row[tid] + acc;

    {
        float s1 = val, s2 = val * val;
        #pragma unroll
        for (int o = 16; o; o >>= 1) {
            s1 += __shfl_xor_sync(0xffffffffu, s1, o);
            s2 += __shfl_xor_sync(0xffffffffu, s2, o);
        }
        if (lane == 0) { a1[w] = s1; a2[w] = s2; }
        __syncthreads();
        if (tid == 0) {
            float t1 = 0.f, t2 = 0.f;
            #pragma unroll
            for (int j = 0; j < 8; j++) { t1 += a1[j]; t2 += a2[j]; }
            float mu = t1 * (1.0f / (float)D);
            stat[0] = mu;
            stat[1] = rsqrtf(t2 * (1.0f / (float)D) - mu * mu + 1e-5f);
        }
        __syncthreads();
        hb1[tid] = (val - stat[0]) * stat[1] * ln1g[tid] + ln1b[tid];
        __syncthreads();
    }

    #pragma unroll
    for (int jj = 0; jj < 4; jj++) {
        int j = tid + jj * 256;
        float a = bf1[j];
        for (int dd = 0; dd < D; dd++) a = fmaf(hb1[dd], ff1[(size_t)dd * DFF + j], a);
        yb[j] = fmaxf(a, 0.0f);
    }
    __syncthreads();

    float acc2 = bf2[tid];
    for (int dd = 0; dd < DFF; dd++) acc2 = fmaf(yb[dd], ff2[(size_t)dd * D + tid], acc2);
    float val2 = hb1[tid] + acc2;
    {
        float s1 = val2, s2 = val2 * val2;
        #pragma unroll
        for (int o = 16; o; o >>= 1) {
            s1 += __shfl_xor_sync(0xffffffffu, s1, o);
            s2 += __shfl_xor_sync(0xffffffffu, s2, o);
        }
        __syncthreads();
        if (lane == 0) { a1[w] = s1; a2[w] = s2; }
        __syncthreads();
        if (tid == 0) {
            float t1 = 0.f, t2 = 0.f;
            #pragma unroll
            for (int j = 0; j < 8; j++) { t1 += a1[j]; t2 += a2[j]; }
            float mu = t1 * (1.0f / (float)D);
            stat[0] = mu;
            stat[1] = rsqrtf(t2 * (1.0f / (float)D) - mu * mu + 1e-5f);
        }
        __syncthreads();
        hb2[tid] = (val2 - stat[0]) * stat[1] * ln2g[tid] + ln2b[tid];
        __syncthreads();
    }

    __shared__ float th[64];
    if (tid < 64) {
        float a = b1[tid];
        for (int dd = 0; dd < D; dd++) a = fmaf(hb2[dd], w1[dd * 64 + tid], a);
        th[tid] = fmaxf(a, 0.0f) * w2[tid];
    }
    __syncthreads();
    if (tid < 32) {
        float s = th[tid] + th[tid + 32];
        #pragma unroll
        for (int o = 16; o; o >>= 1) s += __shfl_xor_sync(0xffffffffu, s, o);
        if (tid == 0) out[b] = s + b2[0];
    }
}

// ===================================================================================
extern "C" void kernel_launch(void* const* d_in, const int* in_sizes, int n_in,
                              void* d_out, int out_size)
{
    const float* x     = (const float*)d_in[0];
    const int*   idx   = (const int*)  d_in[1];
    const float* w_in  = (const float*)d_in[2];
    const float* b_in  = (const float*)d_in[3];
    const float* wq    = (const float*)d_in[4];
    const float* bq    = (const float*)d_in[5];
    const float* wk    = (const float*)d_in[6];
    const float* bk    = (const float*)d_in[7];
    const float* wv    = (const float*)d_in[8];
    const float* bv    = (const float*)d_in[9];
    const float* wo    = (const float*)d_in[10];
    const float* bo    = (const float*)d_in[11];
    const float* w_ff1 = (const float*)d_in[12];
    const float* b_ff1 = (const float*)d_in[13];
    const float* w_ff2 = (const float*)d_in[14];
    const float* b_ff2 = (const float*)d_in[15];
    const float* ln1_g = (const float*)d_in[16];
    const float* ln1_b = (const float*)d_in[17];
    const float* ln2_g = (const float*)d_in[18];
    const float* ln2_b = (const float*)d_in[19];
    const float* w_fc1 = (const float*)d_in[20];
    const float* b_fc1 = (const float*)d_in[21];
    const float* w_fc2 = (const float*)d_in[22];
    const float* b_fc2 = (const float*)d_in[23];
    float* out = (float*)d_out;

    float *h, *q, *k, *v, *nx, *Mv, *vm, *ctxl, *base, *am, *al, *av; int* top;
    __nv_bfloat16 *xhi, *xlo, *hhi, *hlo, *fhi, *flo, *whi, *wlo;
    cudaGetSymbolAddress((void**)&h,   g_h);
    cudaGetSymbolAddress((void**)&q,   g_q);
    cudaGetSymbolAddress((void**)&k,   g_k);
    cudaGetSymbolAddress((void**)&v,   g_v);
    cudaGetSymbolAddress((void**)&nx,  g_nx);
    cudaGetSymbolAddress((void**)&Mv,  g_M);
    cudaGetSymbolAddress((void**)&top, g_top);
    cudaGetSymbolAddress((void**)&vm,  g_vm);
    cudaGetSymbolAddress((void**)&ctxl, g_ctxl);
    cudaGetSymbolAddress((void**)&base, g_base);
    cudaGetSymbolAddress((void**)&am,  g_am);
    cudaGetSymbolAddress((void**)&al,  g_al);
    cudaGetSymbolAddress((void**)&av,  g_av);
    cudaGetSymbolAddress((void**)&xhi, g_x_hi);  cudaGetSymbolAddress((void**)&xlo, g_x_lo);
    cudaGetSymbolAddress((void**)&hhi, g_h_hi);  cudaGetSymbolAddress((void**)&hlo, g_h_lo);
    cudaGetSymbolAddress((void**)&fhi, g_ff_hi); cudaGetSymbolAddress((void**)&flo, g_ff_lo);
    cudaGetSymbolAddress((void**)&whi, g_wt_hi); cudaGetSymbolAddress((void**)&wlo, g_wt_lo);

    cudaFuncSetAttribute(mma_gemm_bf16, cudaFuncAttributeMaxDynamicSharedMemorySize, GEMM_SMEM_V4);

    const int Mrows = B_ * L_;
    dim3 gD  (D / 128,   Mrows / 128);
    dim3 gQKV(3 * D / 128, Mrows / 128);
    dim3 gFF (DFF / 128, Mrows / 128);
    dim3 tb(32, 8);

    const size_t o_in = 0;
    auto o_q  = [&](int l){ return (size_t)FIN * D + (size_t)l * LYR_SZ; };
    auto o_f1 = [&](int l){ return o_q(l) + 262144; };
    auto o_f2 = [&](int l){ return o_q(l) + 524288; };

    split_kernel<<<(B_ * L_ * FIN) / 512, 256>>>(x, xhi, xlo, B_ * L_ * FIN);
    transpose_all_kernel<<<1544, tb>>>(w_in, wq, wk, wv, wo, w_ff1, w_ff2, whi, wlo);
    mma_gemm_bf16<<<gD, 256, GEMM_SMEM_V4>>>(xhi, xlo, whi + o_in, wlo + o_in,
        b_in, nullptr, nullptr, h, nullptr, nullptr, hhi, hlo, nullptr, Mrows, D, FIN, 0, 3, 0);

    // ---------------- layer 0 (full, with wo factorization) ----------------
    {
        const int layer = 0;
        const int* ixL = idx;

        mma_gemm_bf16<<<gQKV, 256, GEMM_SMEM_V4>>>(hhi, hlo, whi + o_q(layer), wlo + o_q(layer),
            bq, bk, bv, q, k, v, nullptr, nullptr, nullptr, Mrows, 768, D, 0, 1, 1);

        qkvm_kernel<<<QK_BLOCKS + B_ * H_, 256>>>(q, k, ixL, Mv, v, vm);
        topk_kernel<<<B_ * H_, 256>>>(Mv, top);
        attn_part_kernel<<<B_ * H_ * 4, 256>>>(q, k, v, top, am, al, av);

        base_kernel<<<B_, 256>>>(vm, wo, bo, base);
        basefill_kernel<<<(B_ * L_ * D) / 512, 256>>>(h, base, nx);
        corr_kernel<<<B_ * H_, 256>>>(top, am, al, av, vm, wo, nx);
        add_ln_kernel<<<Mrows / 2, 256>>>(nx, ln1_g, ln1_b, h, hhi, hlo);

        mma_gemm_bf16<<<gFF, 256, GEMM_SMEM_V4>>>(hhi, hlo, whi + o_f1(layer), wlo + o_f1(layer),
            b_ff1, nullptr, nullptr, nullptr, nullptr, nullptr, fhi, flo, nullptr,
            Mrows, DFF, D, 1, 2, 0);
        mma_gemm_bf16<<<gD, 256, GEMM_SMEM_V4>>>(fhi, flo, whi + o_f2(layer), wlo + o_f2(layer),
            b_ff2, nullptr, nullptr, nx, nullptr, nullptr, nullptr, nullptr, h,
            Mrows, D, DFF, 0, 1, 0);
        add_ln_kernel<<<Mrows / 2, 256>>>(nx, ln2_g, ln2_b, h, hhi, hlo);
    }

    // ---------------- layer 1 (output-funnel pruned) ----------------
    {
        const int layer = 1;
        const int* ixL = idx + (size_t)L_ * S_;

        mma_gemm_bf16<<<gQKV, 256, GEMM_SMEM_V4>>>(hhi, hlo, whi + o_q(layer), wlo + o_q(layer),
            bq + D, bk + D, bv + D, q, k, v, nullptr, nullptr, nullptr, Mrows, 768, D, 0, 1, 1);

        qkvm_kernel<<<QK_BLOCKS + B_ * H_, 256>>>(q, k, ixL, Mv, v, vm);
        topk_kernel<<<B_ * H_, 256>>>(Mv, top);
        last_attn_kernel<<<B_ * H_, 256>>>(q, k, v, top, vm, ctxl);

        final_head_kernel<<<B_, 256>>>(h, ctxl,
            wo + (size_t)D * D, bo + D,
            ln1_g + D, ln1_b + D,
            w_ff1 + (size_t)D * DFF, b_ff1 + DFF,
            w_ff2 + (size_t)DFF * D, b_ff2 + D,
            ln2_g + D, ln2_b + D,
            w_fc1, b_fc1, w_fc2, b_fc2, out);
    }
}

// round 13
// speedup vs baseline: 1.0482x; 1.0482x over previous
#include <cuda_runtime.h>
#include <cuda_bf16.h>
#include <cstdint>
#include <math.h>

// Problem constants
#define B_   8
#define L_   2048
#define FIN  32
#define D    256
#define H_   8
#define DH   32
#define DFF  1024
#define S_   40
#define U_   40
#define NL   2

// ---------------- scratch (device globals; no allocation allowed) ----------------
__device__ float g_h  [B_*L_*D];
__device__ float g_q  [B_*L_*D];
__device__ float g_k  [B_*L_*D];
__device__ float g_v  [B_*L_*D];
__device__ float g_nx [B_*L_*D];
__device__ float g_M  [B_*H_*L_];
__device__ int   g_top[B_*H_*U_];
__device__ int   g_member[B_*H_];
__device__ float g_vm [B_*H_*DH];
__device__ float g_ctxl[B_*H_*DH];
__device__ float g_am[B_*H_*4*U_];
__device__ float g_al[B_*H_*4*U_];
__device__ float g_av[B_*H_*4*U_*DH];

// bf16 hi/lo planes (K-chunked layout: [K/32][rows][32] with in-chunk swizzle)
__device__ __nv_bfloat16 g_x_hi [B_*L_*FIN], g_x_lo [B_*L_*FIN];
__device__ __nv_bfloat16 g_h_hi [B_*L_*D],   g_h_lo [B_*L_*D];
__device__ __nv_bfloat16 g_ctx_hi[B_*L_*D],  g_ctx_lo[B_*L_*D];
__device__ __nv_bfloat16 g_ff_hi[B_*L_*DFF], g_ff_lo[B_*L_*DFF];
#define LYR_SZ   786432
#define WT_TOTAL (FIN*D + NL*LYR_SZ)
__device__ __nv_bfloat16 g_wt_hi[WT_TOTAL], g_wt_lo[WT_TOTAL];

// =========================== helpers ===============================================
__device__ __forceinline__ uint32_t smem_u32(const void* p) {
    uint32_t a;
    asm("{ .reg .u64 t; cvta.to.shared.u64 t, %1; cvt.u32.u64 %0, t; }" : "=r"(a) : "l"(p));
    return a;
}
__device__ __forceinline__ void split2(float x, float y, uint32_t& hi, uint32_t& lo) {
    __nv_bfloat162 h = __float22bfloat162_rn(make_float2(x, y));
    float2 hf = __bfloat1622float2(h);
    __nv_bfloat162 l = __float22bfloat162_rn(make_float2(x - hf.x, y - hf.y));
    hi = *(uint32_t*)&h; lo = *(uint32_t*)&l;
}
__device__ __forceinline__ void split_scalar(float v, __nv_bfloat16* hp, __nv_bfloat16* lp) {
    __nv_bfloat16 hb = __float2bfloat16(v);
    *hp = hb;
    *lp = __float2bfloat16(v - __bfloat162float(hb));
}

// chunked-plane index: element (row, k) in a tensor with Md rows
__device__ __forceinline__ size_t pidx(int row, int k, int Md) {
    int c = k >> 5, u = (k >> 3) & 3, e = k & 7;
    int u2 = u ^ ((row >> 1) & 3);
    return ((size_t)c * Md + row) * 32 + u2 * 8 + e;
}

#define MMA_BF16(c, a, b)                                                        \
    asm volatile("mma.sync.aligned.m16n8k16.row.col.f32.bf16.bf16.f32 "          \
        "{%0,%1,%2,%3}, {%4,%5,%6,%7}, {%8,%9}, {%0,%1,%2,%3};"                  \
        : "+f"((c)[0]), "+f"((c)[1]), "+f"((c)[2]), "+f"((c)[3])                  \
        : "r"((a)[0]), "r"((a)[1]), "r"((a)[2]), "r"((a)[3]),                     \
          "r"((b)[0]), "r"((b)[1]))

#define LDM4(r, addr)                                                            \
    asm volatile("ldmatrix.sync.aligned.m8n8.x4.shared.b16 {%0,%1,%2,%3}, [%4];" \
        : "=r"((r)[0]), "=r"((r)[1]), "=r"((r)[2]), "=r"((r)[3]) : "r"(addr))

#define MBAR_INIT(mb, n)  asm volatile("mbarrier.init.shared.b64 [%0], %1;" :: "r"(mb), "r"(n) : "memory")
#define MBAR_EXPECT(mb, tx) asm volatile("mbarrier.arrive.expect_tx.shared.b64 _, [%0], %1;" :: "r"(mb), "r"(tx) : "memory")
#define MBAR_WAIT(mb, ph) do {                                                          \
    asm volatile("{ .reg .pred P;\n\t"                                                  \
        "W_%=: mbarrier.try_wait.parity.acquire.cta.shared::cta.b64 P, [%0], %1, 0x989680;\n\t" \
        "@P bra.uni DN_%=; bra.uni W_%=; DN_%=: }"                                      \
        :: "r"(mb), "r"(ph) : "memory");                                                \
} while (0)
#define BULK_LD(dst, src, bytes, mb)                                                    \
    asm volatile("cp.async.bulk.shared::cluster.global.mbarrier::complete_tx::bytes "   \
        "[%0], [%1], %2, [%3];" :: "r"(dst), "l"(src), "r"(bytes), "r"(mb) : "memory")

// ======= 3-stage pipelined bf16x3 GEMM: bulk-copy loads, chunked operand planes ====
#define STAGE_B 32768
#define GEMM_SMEM_V4 (1024 + 3*STAGE_B)

__global__ __launch_bounds__(256, 2)
void mma_gemm_bf16(const __nv_bfloat16* __restrict__ Ahi, const __nv_bfloat16* __restrict__ Alo,
                   const __nv_bfloat16* __restrict__ Bhi, const __nv_bfloat16* __restrict__ Blo,
                   const float* __restrict__ b0, const float* __restrict__ b1,
                   const float* __restrict__ b2,
                   float* __restrict__ C0, float* __restrict__ C1, float* __restrict__ C2,
                   __nv_bfloat16* __restrict__ Chi, __nv_bfloat16* __restrict__ Clo,
                   const float* __restrict__ Radd,
                   int M, int N, int K, int relu, int mode, int split3)
{
    extern __shared__ uint32_t sm[];
    int tid  = threadIdx.x;
    int brow = blockIdx.y * 128;
    int bcol = blockIdx.x * 128;
    int w = tid >> 5, lane = tid & 31;
    int gid = lane >> 2, tig = lane & 3;
    int moff = (w >> 1) * 32, noff = (w & 1) * 64;
    uint32_t smb = smem_u32(sm);
    uint32_t stg = smb + 1024;

    if (tid == 0) {
        MBAR_INIT(smb,      1);
        MBAR_INIT(smb + 8,  1);
        MBAR_INIT(smb + 16, 1);
    }
    __syncthreads();

    int mat = lane >> 3, r8 = lane & 7;
    uint32_t aoffk[2][2], boffk[4][2];
    #pragma unroll
    for (int mt = 0; mt < 2; mt++) {
        int row = moff + mt * 16 + (mat & 1) * 8 + r8;
        int sw = (row >> 1) & 3;
        #pragma unroll
        for (int ks = 0; ks < 2; ks++) {
            int u = ks * 2 + (mat >> 1);
            aoffk[mt][ks] = (uint32_t)(row * 64 + ((u ^ sw) << 4));
        }
    }
    #pragma unroll
    for (int p = 0; p < 4; p++) {
        int row = noff + p * 16 + (mat >> 1) * 8 + r8;
        int sw = (row >> 1) & 3;
        #pragma unroll
        for (int ks = 0; ks < 2; ks++) {
            int u = ks * 2 + (mat & 1);
            boffk[p][ks] = (uint32_t)(row * 64 + ((u ^ sw) << 4));
        }
    }

    const int NC = K >> 5;

    auto issue = [&](int c) {
        int s = c % 3;
        uint32_t sb = stg + (uint32_t)s * STAGE_B;
        uint32_t mb = smb + (uint32_t)s * 8;
        MBAR_EXPECT(mb, 32768u);
        const __nv_bfloat16* a0 = Ahi + ((size_t)c * M + brow) * 32;
        const __nv_bfloat16* a1 = Alo + ((size_t)c * M + brow) * 32;
        const __nv_bfloat16* b0p = Bhi + ((size_t)c * N + bcol) * 32;
        const __nv_bfloat16* b1p = Blo + ((size_t)c * N + bcol) * 32;
        BULK_LD(sb,          a0,  8192u, mb);
        BULK_LD(sb + 8192,   a1,  8192u, mb);
        BULK_LD(sb + 16384,  b0p, 8192u, mb);
        BULK_LD(sb + 24576,  b1p, 8192u, mb);
    };

    if (tid == 0) {
        issue(0);
        if (NC > 1) issue(1);
    }

    float acc[2][8][4] = {};

    for (int c = 0; c < NC; c++) {
        __syncthreads();
        if (tid == 0 && c + 2 < NC) issue(c + 2);
        MBAR_WAIT(smb + (uint32_t)(c % 3) * 8, (c / 3) & 1);

        uint32_t bb = stg + (uint32_t)(c % 3) * STAGE_B;
        uint32_t Ahb = bb, Alb = bb + 8192, Bhb = bb + 16384, Blb = bb + 24576;

        #pragma unroll
        for (int ks = 0; ks < 2; ks++) {
            uint32_t afh[2][4], afl[2][4];
            #pragma unroll
            for (int mt = 0; mt < 2; mt++) {
                LDM4(afh[mt], Ahb + aoffk[mt][ks]);
                LDM4(afl[mt], Alb + aoffk[mt][ks]);
            }
            #pragma unroll
            for (int p = 0; p < 4; p++) {
                uint32_t bfh[4], bfl[4];
                LDM4(bfh, Bhb + boffk[p][ks]);
                LDM4(bfl, Blb + boffk[p][ks]);
                #pragma unroll
                for (int mt = 0; mt < 2; mt++)
                    #pragma unroll
                    for (int hf = 0; hf < 2; hf++) {
                        int nt = p * 2 + hf;
                        MMA_BF16(acc[mt][nt], afh[mt], &bfh[hf * 2]);
                        MMA_BF16(acc[mt][nt], afh[mt], &bfl[hf * 2]);
                        MMA_BF16(acc[mt][nt], afl[mt], &bfh[hf * 2]);
                    }
            }
        }
    }

    float* Cf; const float* bp_; int cb, Nst;
    if (split3) {
        int mi = bcol >> 8;
        Cf  = (mi == 0) ? C0 : (mi == 1 ? C1 : C2);
        bp_ = (mi == 0) ? b0 : (mi == 1 ? b1 : b2);
        cb = bcol & 255; Nst = 256;
    } else {
        Cf = C0; bp_ = b0; cb = bcol; Nst = N;
    }

    #pragma unroll
    for (int mt = 0; mt < 2; mt++) {
        int r0 = brow + moff + mt * 16 + gid;
        #pragma unroll
        for (int nt = 0; nt < 8; nt++) {
            int c = cb + noff + nt * 8 + tig * 2;
            float bb0 = bp_[c], bb1 = bp_[c + 1];
            float2 o0 = make_float2(acc[mt][nt][0] + bb0, acc[mt][nt][1] + bb1);
            float2 o1 = make_float2(acc[mt][nt][2] + bb0, acc[mt][nt][3] + bb1);
            size_t i0 = (size_t)r0 * Nst + c;
            size_t i1 = (size_t)(r0 + 8) * Nst + c;
            if (Radd) {
                float2 ra0 = *(const float2*)(Radd + i0);
                float2 ra1 = *(const float2*)(Radd + i1);
                o0.x += ra0.x; o0.y += ra0.y;
                o1.x += ra1.x; o1.y += ra1.y;
            }
            if (relu) {
                o0.x = fmaxf(o0.x, 0.f); o0.y = fmaxf(o0.y, 0.f);
                o1.x = fmaxf(o1.x, 0.f); o1.y = fmaxf(o1.y, 0.f);
            }
            if (mode & 1) {
                *(float2*)(Cf + i0) = o0;
                *(float2*)(Cf + i1) = o1;
            }
            if (mode & 2) {
                uint32_t h0, l0, h1, l1;
                split2(o0.x, o0.y, h0, l0);
                split2(o1.x, o1.y, h1, l1);
                size_t p0 = pidx(r0,     c, 16384);
                size_t p1 = pidx(r0 + 8, c, 16384);
                *(uint32_t*)(Chi + p0) = h0; *(uint32_t*)(Clo + p0) = l0;
                *(uint32_t*)(Chi + p1) = h1; *(uint32_t*)(Clo + p1) = l1;
            }
        }
    }
}

// ---------------- batched transpose+split of ALL weights (chunked layout) ----------
__global__ void transpose_all_kernel(const float* __restrict__ w_in,
                                     const float* __restrict__ wq, const float* __restrict__ wk,
                                     const float* __restrict__ wv, const float* __restrict__ wo,
                                     const float* __restrict__ f1, const float* __restrict__ f2,
                                     __nv_bfloat16* __restrict__ hi, __nv_bfloat16* __restrict__ lo)
{
    const int start[14] = {0, 8, 72, 136, 200, 264, 520, 776, 840, 904, 968, 1032, 1288, 1544};
    int t = blockIdx.x;
    int m = 0;
    #pragma unroll
    for (int i = 1; i < 14; i++) if (t >= start[i]) m = i;
    int layer = (m >= 7) ? 1 : 0;
    int mi = (m == 0) ? 0 : ((m - 1) % 6) + 1;
    const float* src; int K, N, Nchunk, nofs; size_t dst;
    size_t base = (size_t)FIN * D + (size_t)layer * LYR_SZ;
    switch (mi) {
        case 0: src = w_in;                          K = FIN; N = D;   Nchunk = 256;  nofs = 0;   dst = 0;             break;
        case 1: src = wq + (size_t)layer * D * D;    K = D;   N = D;   Nchunk = 768;  nofs = 0;   dst = base;          break;
        case 2: src = wk + (size_t)layer * D * D;    K = D;   N = D;   Nchunk = 768;  nofs = 256; dst = base;          break;
        case 3: src = wv + (size_t)layer * D * D;    K = D;   N = D;   Nchunk = 768;  nofs = 512; dst = base;          break;
        case 4: src = wo + (size_t)layer * D * D;    K = D;   N = D;   Nchunk = 256;  nofs = 0;   dst = base + 196608; break;
        case 5: src = f1 + (size_t)layer * D * DFF;  K = D;   N = DFF; Nchunk = 1024; nofs = 0;   dst = base + 262144; break;
        default:src = f2 + (size_t)layer * DFF * D;  K = DFF; N = D;   Nchunk = 256;  nofs = 0;   dst = base + 524288; break;
    }
    int lt = t - start[m];
    int ntn = N >> 5;
    int nb = (lt % ntn) << 5, kb = (lt / ntn) << 5;

    __shared__ float tbuf[32][33];
    int tx = threadIdx.x, ty = threadIdx.y;
    #pragma unroll
    for (int i = ty; i < 32; i += 8)
        tbuf[i][tx] = src[(size_t)(kb + i) * N + nb + tx];
    __syncthreads();
    #pragma unroll
    for (int i = ty; i < 32; i += 8) {
        float v = tbuf[tx][i];
        size_t o = dst + pidx(nofs + nb + i, kb + tx, Nchunk);
        split_scalar(v, hi + o, lo + o);
    }
}

// ---------------- plain split ------------------------------------------------------
__global__ void split_kernel(const float* __restrict__ in,
                             __nv_bfloat16* __restrict__ hi,
                             __nv_bfloat16* __restrict__ lo, int n)
{
    int i = (blockIdx.x * blockDim.x + threadIdx.x) * 2;
    if (i >= n) return;
    float2 v = *(const float2*)(in + i);
    uint32_t h, l;
    split2(v.x, v.y, h, l);
    size_t o = pidx(i >> 5, i & 31, 16384);
    *(uint32_t*)(hi + o) = h;
    *(uint32_t*)(lo + o) = l;
}

// -------- fused sampled-QK M-score + v-mean ----------------------------------------
#define QK_BLOCKS (B_*H_*L_/8)
__global__ void qkvm_kernel(const float* __restrict__ q, const float* __restrict__ k,
                            const int* __restrict__ idx, float* __restrict__ Mout,
                            const float* __restrict__ v, float* __restrict__ vm)
{
    if (blockIdx.x < QK_BLOCKS) {
        int gw   = (blockIdx.x * blockDim.x + threadIdx.x) >> 5;
        int lane = threadIdx.x & 31;
        int l  = gw & (L_ - 1);
        int bh = gw >> 11;
        int b  = bh >> 3, h = bh & 7;

        int g  = lane >> 3;
        int d4 = (lane & 7) << 2;
        float4 q4 = *(const float4*)(q + ((size_t)b * L_ + l) * D + h * DH + d4);
        const float* kbase = k + (size_t)b * L_ * D + h * DH;
        const int*   irow  = idx + l * S_;

        float mx = -1e30f, sm = 0.0f;
        #pragma unroll 5
        for (int s0 = 0; s0 < S_; s0 += 4) {
            int ki = __ldg(&irow[s0 + g]);
            float4 kv = *(const float4*)(kbase + (size_t)ki * D + d4);
            float p = q4.x * kv.x + q4.y * kv.y + q4.z * kv.z + q4.w * kv.w;
            p += __shfl_xor_sync(0xffffffffu, p, 1);
            p += __shfl_xor_sync(0xffffffffu, p, 2);
            p += __shfl_xor_sync(0xffffffffu, p, 4);
            mx = fmaxf(mx, p);
            sm += p;
        }
        mx = fmaxf(mx, __shfl_xor_sync(0xffffffffu, mx, 8));
        mx = fmaxf(mx, __shfl_xor_sync(0xffffffffu, mx, 16));
        sm += __shfl_xor_sync(0xffffffffu, sm, 8);
        sm += __shfl_xor_sync(0xffffffffu, sm, 16);
        if (lane == 0) Mout[gw] = mx - sm * (1.0f / (float)L_);
    } else {
        int bh = blockIdx.x - QK_BLOCKS; int b = bh >> 3, h = bh & 7;
        int tid = threadIdx.x;
        int d = tid & 31, seg = tid >> 5;
        const float* vb = v + (size_t)b * L_ * D + h * DH + d;
        float acc = 0.0f;
        for (int l = seg; l < L_; l += 8) acc += vb[(size_t)l * D];
        __shared__ float sp[8][32];
        sp[seg][d] = acc;
        __syncthreads();
        if (tid < 32) {
            float s = 0.0f;
            #pragma unroll
            for (int i = 0; i < 8; i++) s += sp[i][tid];
            vm[bh * DH + tid] = s * (1.0f / (float)L_);
        }
    }
}

// ---------------- top-40 per (b,h) (layer 0 only) -----------------------------------
__global__ void topk_kernel(const float* __restrict__ Mv, int* __restrict__ top)
{
    int bh  = blockIdx.x;
    int tid = threadIdx.x;
    int w = tid >> 5, lane = tid & 31;
    __shared__ float sv[L_];
    __shared__ float wv_[8];
    __shared__ int   wi_[8];
    for (int i = tid; i < L_; i += 256) sv[i] = Mv[(size_t)bh * L_ + i];
    __syncthreads();

    for (int r = 0; r < U_; r++) {
        float bv = -1e30f; int bi = 0x7fffffff;
        #pragma unroll
        for (int j = 0; j < 8; j++) {
            int i = tid + j * 256;
            float v = sv[i];
            if (v > bv || (v == bv && i < bi)) { bv = v; bi = i; }
        }
        #pragma unroll
        for (int o = 16; o; o >>= 1) {
            float ov = __shfl_xor_sync(0xffffffffu, bv, o);
            int   oi = __shfl_xor_sync(0xffffffffu, bi, o);
            if (ov > bv || (ov == bv && oi < bi)) { bv = ov; bi = oi; }
        }
        if (lane == 0) { wv_[w] = bv; wi_[w] = bi; }
        __syncthreads();
        if (tid == 0) {
            float fv = wv_[0]; int fi = wi_[0];
            #pragma unroll
            for (int j = 1; j < 8; j++) {
                float ov = wv_[j]; int oi = wi_[j];
                if (ov > fv || (ov == fv && oi < fi)) { fv = ov; fi = oi; }
            }
            top[bh * U_ + r] = fi;
            sv[fi] = -1e30f;
        }
        __syncthreads();
    }
}

// ------- layer-1 membership: is row L-1 in the top-40 of M? (rank test) -------------
__global__ void member_kernel(const float* __restrict__ Mv, int* __restrict__ member)
{
    int bh  = blockIdx.x;
    int tid = threadIdx.x;
    int w = tid >> 5, lane = tid & 31;
    __shared__ int wc[8];
    float mref = Mv[(size_t)bh * L_ + (L_ - 1)];
    int c = 0;
    // ties (v == mref) at i < L-1 outrank index L-1 (lower index wins)
    for (int i = tid; i < L_ - 1; i += 256)
        if (Mv[(size_t)bh * L_ + i] >= mref) c++;
    #pragma unroll
    for (int o = 16; o; o >>= 1) c += __shfl_xor_sync(0xffffffffu, c, o);
    if (lane == 0) wc[w] = c;
    __syncthreads();
    if (tid == 0) {
        int t = 0;
        #pragma unroll
        for (int j = 0; j < 8; j++) t += wc[j];
        member[bh] = (t < U_) ? 1 : 0;
    }
}

// ---------------- fill ctx planes with broadcast v-mean (chunked) ------------------
__global__ void ctxfill_kernel(const float* __restrict__ vm,
                               __nv_bfloat16* __restrict__ chi,
                               __nv_bfloat16* __restrict__ clo)
{
    int i4 = (blockIdx.x * blockDim.x + threadIdx.x) * 4;
    if (i4 >= B_ * L_ * D) return;
    int dfull = i4 & (D - 1);
    int b = i4 / (L_ * D);
    int h = dfull >> 5, d = dfull & 31;
    float4 v = *(const float4*)(vm + ((b << 3) + h) * DH + d);
    uint32_t h01, h23, l01, l23;
    split2(v.x, v.y, h01, l01);
    split2(v.z, v.w, h23, l23);
    size_t o = pidx(i4 >> 8, dfull, 16384);
    *(uint2*)(chi + o) = make_uint2(h01, h23);
    *(uint2*)(clo + o) = make_uint2(l01, l23);
}

// --------- split-KV flash attention part: 4 splits of 512 keys per (b,h) ----------
__global__ __launch_bounds__(256, 1)
void attn_part_kernel(const float* __restrict__ q, const float* __restrict__ k,
                      const float* __restrict__ v, const int* __restrict__ top,
                      float* __restrict__ am, float* __restrict__ al,
                      float* __restrict__ av)
{
    __shared__ float Ks[128][33];
    __shared__ float Vs[128][33];
    __shared__ float qs[40][32];
    __shared__ float ps[8][128];
    __shared__ int   stop[40];

    int blk = blockIdx.x;
    int sp = blk & 3, bh = blk >> 2;
    int b = bh >> 3, h = bh & 7;
    int tid = threadIdx.x, w = tid >> 5, lane = tid & 31;

    if (tid < 40) stop[tid] = top[bh * U_ + tid];
    __syncthreads();
    for (int i = tid; i < 40 * 32; i += 256) {
        int u = i >> 5, d = i & 31;
        qs[u][d] = q[((size_t)b * L_ + stop[u]) * D + h * DH + d];
    }

    float m[5], l[5], acc[5];
    #pragma unroll
    for (int j = 0; j < 5; j++) { m[j] = -1e30f; l[j] = 0.f; acc[j] = 0.f; }
    const float scale = 0.1767766952966369f;
    const float* kb = k + (size_t)b * L_ * D + h * DH;
    const float* vb = v + (size_t)b * L_ * D + h * DH;
    __syncthreads();

    int tstart = sp * 512;
    for (int t0 = tstart; t0 < tstart + 512; t0 += 128) {
        for (int i = tid; i < 128 * 32; i += 256) {
            int r = i >> 5, d = i & 31;
            Ks[r][d] = kb[(size_t)(t0 + r) * D + d];
            Vs[r][d] = vb[(size_t)(t0 + r) * D + d];
        }
        __syncthreads();

        float sj[5][4];
        #pragma unroll
        for (int j = 0; j < 5; j++)
            #pragma unroll
            for (int i = 0; i < 4; i++) sj[j][i] = 0.f;
        #pragma unroll
        for (int d = 0; d < 32; d++) {
            float k0v = Ks[lane][d], k1v = Ks[lane + 32][d];
            float k2v = Ks[lane + 64][d], k3v = Ks[lane + 96][d];
            #pragma unroll
            for (int j = 0; j < 5; j++) {
                float qd = qs[w * 5 + j][d];
                sj[j][0] = fmaf(qd, k0v, sj[j][0]);
                sj[j][1] = fmaf(qd, k1v, sj[j][1]);
                sj[j][2] = fmaf(qd, k2v, sj[j][2]);
                sj[j][3] = fmaf(qd, k3v, sj[j][3]);
            }
        }
        #pragma unroll
        for (int j = 0; j < 5; j++) {
            float s0 = sj[j][0] * scale, s1 = sj[j][1] * scale;
            float s2 = sj[j][2] * scale, s3 = sj[j][3] * scale;
            float tm = fmaxf(fmaxf(s0, s1), fmaxf(s2, s3));
            #pragma unroll
            for (int o = 16; o; o >>= 1) tm = fmaxf(tm, __shfl_xor_sync(0xffffffffu, tm, o));
            float mn   = fmaxf(m[j], tm);
            float corr = __expf(m[j] - mn);
            float p0 = __expf(s0 - mn), p1 = __expf(s1 - mn);
            float p2 = __expf(s2 - mn), p3 = __expf(s3 - mn);
            float psum = p0 + p1 + p2 + p3;
            #pragma unroll
            for (int o = 16; o; o >>= 1) psum += __shfl_xor_sync(0xffffffffu, psum, o);
            l[j] = l[j] * corr + psum;
            m[j] = mn;
            ps[w][lane] = p0; ps[w][lane + 32] = p1; ps[w][lane + 64] = p2; ps[w][lane + 96] = p3;
            __syncwarp();
            float aa = acc[j] * corr;
            const float4* pv4 = (const float4*)ps[w];
            #pragma unroll 8
            for (int kk4 = 0; kk4 < 32; kk4++) {
                float4 p4 = pv4[kk4];
                int kk = kk4 * 4;
                aa = fmaf(p4.x, Vs[kk][lane],     aa);
                aa = fmaf(p4.y, Vs[kk + 1][lane], aa);
                aa = fmaf(p4.z, Vs[kk + 2][lane], aa);
                aa = fmaf(p4.w, Vs[kk + 3][lane], aa);
            }
            acc[j] = aa;
            __syncwarp();
        }
        __syncthreads();
    }
    #pragma unroll
    for (int j = 0; j < 5; j++) {
        int u = w * 5 + j;
        int pidx_ = (bh * 4 + sp) * U_ + u;
        if (lane == 0) { am[pidx_] = m[j]; al[pidx_] = l[j]; }
        av[(size_t)pidx_ * DH + lane] = acc[j];
    }
}

// --------- split-KV combine: merge partials, scatter into ctx planes (chunked) -----
__global__ void attn_combine_kernel(const int* __restrict__ top,
                                    const float* __restrict__ am, const float* __restrict__ al,
                                    const float* __restrict__ av,
                                    __nv_bfloat16* __restrict__ chi, __nv_bfloat16* __restrict__ clo)
{
    int bh = blockIdx.x; int b = bh >> 3, h = bh & 7;
    int tid = threadIdx.x, w = tid >> 5, lane = tid & 31;
    __shared__ int stop[40];
    if (tid < 40) stop[tid] = top[bh * U_ + tid];
    __syncthreads();

    #pragma unroll
    for (int j = 0; j < 5; j++) {
        int u = w * 5 + j;
        int base = bh * 4 * U_ + u;
        float m0 = am[base], m1 = am[base + U_], m2 = am[base + 2*U_], m3 = am[base + 3*U_];
        float ms = fmaxf(fmaxf(m0, m1), fmaxf(m2, m3));
        float e0 = __expf(m0 - ms), e1 = __expf(m1 - ms);
        float e2 = __expf(m2 - ms), e3 = __expf(m3 - ms);
        float Lsum = al[base] * e0 + al[base + U_] * e1 + al[base + 2*U_] * e2 + al[base + 3*U_] * e3;
        float num = av[(size_t)base * DH + lane] * e0
                  + av[(size_t)(base + U_) * DH + lane] * e1
                  + av[(size_t)(base + 2*U_) * DH + lane] * e2
                  + av[(size_t)(base + 3*U_) * DH + lane] * e3;
        float o = num / Lsum;
        size_t off = pidx(b * L_ + stop[u], h * DH + lane, 16384);
        split_scalar(o, chi + off, clo + off);
    }
}

// ---------- LayerNorm of pre-summed input + split (chunked plane writes) -----------
__global__ void add_ln_kernel(const float* __restrict__ sum,
                              const float* __restrict__ g, const float* __restrict__ bb,
                              float* __restrict__ hout,
                              __nv_bfloat16* __restrict__ hhi, __nv_bfloat16* __restrict__ hlo)
{
    int tid = threadIdx.x;
    int rl  = tid >> 7;
    int ct  = tid & 127;
    int row = blockIdx.x * 2 + rl;
    size_t off = (size_t)row * D + ct * 2;
    float2 v = *(const float2*)(sum + off);
    float s1 = v.x + v.y, s2 = v.x * v.x + v.y * v.y;
    #pragma unroll
    for (int o = 16; o; o >>= 1) {
        s1 += __shfl_xor_sync(0xffffffffu, s1, o);
        s2 += __shfl_xor_sync(0xffffffffu, s2, o);
    }
    __shared__ float a1[2][4], a2[2][4], mu[2], rv[2];
    int wr = (tid >> 5) & 3;
    int lane = tid & 31;
    if (lane == 0) { a1[rl][wr] = s1; a2[rl][wr] = s2; }
    __syncthreads();
    if (ct == 0) {
        float t1 = a1[rl][0] + a1[rl][1] + a1[rl][2] + a1[rl][3];
        float t2 = a2[rl][0] + a2[rl][1] + a2[rl][2] + a2[rl][3];
        float m = t1 * (1.0f / (float)D);
        float var = t2 * (1.0f / (float)D) - m * m;
        mu[rl] = m;
        rv[rl] = rsqrtf(var + 1e-5f);
    }
    __syncthreads();
    float m = mu[rl], r = rv[rl];
    float2 gg = *(const float2*)(g + ct * 2);
    float2 b2 = *(const float2*)(bb + ct * 2);
    float2 o;
    o.x = (v.x - m) * r * gg.x + b2.x;
    o.y = (v.y - m) * r * gg.y + b2.y;
    *(float2*)(hout + off) = o;
    uint32_t hi32, lo32;
    split2(o.x, o.y, hi32, lo32);
    size_t po = pidx(row, ct * 2, 16384);
    *(uint32_t*)(hhi + po) = hi32;
    *(uint32_t*)(hlo + po) = lo32;
}

// --------- last-layer attention for row L-1 only (uses membership flag) ------------
__global__ __launch_bounds__(256, 1)
void last_attn_kernel(const float* __restrict__ q, const float* __restrict__ k,
                      const float* __restrict__ v, const int* __restrict__ member,
                      const float* __restrict__ vm, float* __restrict__ ctxl)
{
    int bh = blockIdx.x; int b = bh >> 3, h = bh & 7;
    int tid = threadIdx.x;
    __shared__ float qs[DH];
    __shared__ float sc[L_];
    __shared__ float red[256];
    __shared__ float part[8][DH];

    if (!member[bh]) {
        if (tid < DH) ctxl[bh * DH + tid] = vm[bh * DH + tid];
        return;
    }

    if (tid < DH) qs[tid] = q[((size_t)b * L_ + (L_ - 1)) * D + h * DH + tid];
    __syncthreads();

    const float* kb = k + (size_t)b * L_ * D + h * DH;
    const float scale = 0.1767766952966369f;
    float lmax = -1e30f;
    for (int l = tid; l < L_; l += 256) {
        const float4* kr = (const float4*)(kb + (size_t)l * D);
        float dot = 0.0f;
        #pragma unroll
        for (int j = 0; j < 8; j++) {
            float4 kv = __ldg(&kr[j]);
            dot += qs[4*j+0]*kv.x + qs[4*j+1]*kv.y + qs[4*j+2]*kv.z + qs[4*j+3]*kv.w;
        }
        dot *= scale;
        sc[l] = dot;
        lmax = fmaxf(lmax, dot);
    }
    red[tid] = lmax; __syncthreads();
    for (int s = 128; s; s >>= 1) { if (tid < s) red[tid] = fmaxf(red[tid], red[tid + s]); __syncthreads(); }
    float gmax = red[0];
    __syncthreads();
    float lsum = 0.0f;
    for (int l = tid; l < L_; l += 256) {
        float e = __expf(sc[l] - gmax);
        sc[l] = e;
        lsum += e;
    }
    red[tid] = lsum; __syncthreads();
    for (int s = 128; s; s >>= 1) { if (tid < s) red[tid] += red[tid + s]; __syncthreads(); }
    float inv = 1.0f / red[0];
    __syncthreads();

    int d = tid & 31, seg = tid >> 5;
    const float* vb = v + (size_t)b * L_ * D + h * DH + d;
    float acc = 0.0f;
    for (int l = seg; l < L_; l += 8) acc += sc[l] * vb[(size_t)l * D];
    part[seg][d] = acc;
    __syncthreads();
    if (tid < DH) {
        float s = 0.0f;
        #pragma unroll
        for (int i = 0; i < 8; i++) s += part[i][tid];
        ctxl[bh * DH + tid] = s * inv;
    }
}

// --------- final chain for row L-1 ---------------------------------------------------
__global__ __launch_bounds__(256, 1)
void final_head_kernel(const float* __restrict__ h, const float* __restrict__ ctxl,
                       const float* __restrict__ wo2, const float* __restrict__ bo2,
                       const float* __restrict__ ln1g, const float* __restrict__ ln1b,
                       const float* __restrict__ ff1, const float* __restrict__ bf1,
                       const float* __restrict__ ff2, const float* __restrict__ bf2,
                       const float* __restrict__ ln2g, const float* __restrict__ ln2b,
                       const float* __restrict__ w1, const float* __restrict__ b1,
                       const float* __restrict__ w2, const float* __restrict__ b2,
                       float* __restrict__ out)
{
    int b = blockIdx.x;
    int tid = threadIdx.x;
    int w = tid >> 5, lane = tid & 31;
    __shared__ float row[D], ctxr[D], hb1[D], yb[DFF], hb2[D];
    __shared__ float a1[8], a2[8], stat[2];

    row[tid]  = h[((size_t)b * L_ + (L_ - 1)) * D + tid];
    ctxr[tid] = ctxl[b * D + tid];
    __syncthreads();

    float acc = bo2[tid];
    for (int dd = 0; dd < D; dd++) acc = fmaf(ctxr[dd], wo2[dd * D + tid], acc);
    float val = row[tid] + acc;

    {
        float s1 = val, s2 = val * val;
        #pragma unroll
        for (int o = 16; o; o >>= 1) {
            s1 += __shfl_xor_sync(0xffffffffu, s1, o);
            s2 += __shfl_xor_sync(0xffffffffu, s2, o);
        }
        if (lane == 0) { a1[w] = s1; a2[w] = s2; }
        __syncthreads();
        if (tid == 0) {
            float t1 = 0.f, t2 = 0.f;
            #pragma unroll
            for (int j = 0; j < 8; j++) { t1 += a1[j]; t2 += a2[j]; }
            float mu = t1 * (1.0f / (float)D);
            stat[0] = mu;
            stat[1] = rsqrtf(t2 * (1.0f / (float)D) - mu * mu + 1e-5f);
        }
        __syncthreads();
        hb1[tid] = (val - stat[0]) * stat[1] * ln1g[tid] + ln1b[tid];
        __syncthreads();
    }

    #pragma unroll
    for (int jj = 0; jj < 4; jj++) {
        int j = tid + jj * 256;
        float a = bf1[j];
        for (int dd = 0; dd < D; dd++) a = fmaf(hb1[dd], ff1[(size_t)dd * DFF + j], a);
        yb[j] = fmaxf(a, 0.0f);
    }
    __syncthreads();

    float acc2 = bf2[tid];
    for (int dd = 0; dd < DFF; dd++) acc2 = fmaf(yb[dd], ff2[(size_t)dd * D + tid], acc2);
    float val2 = hb1[tid] + acc2;
    {
        float s1 = val2, s2 = val2 * val2;
        #pragma unroll
        for (int o = 16; o; o >>= 1) {
            s1 += __shfl_xor_sync(0xffffffffu, s1, o);
            s2 += __shfl_xor_sync(0xffffffffu, s2, o);
        }
        __syncthreads();
        if (lane == 0) { a1[w] = s1; a2[w] = s2; }
        __syncthreads();
        if (tid == 0) {
            float t1 = 0.f, t2 = 0.f;
            #pragma unroll
            for (int j = 0; j < 8; j++) { t1 += a1[j]; t2 += a2[j]; }
            float mu = t1 * (1.0f / (float)D);
            stat[0] = mu;
            stat[1] = rsqrtf(t2 * (1.0f / (float)D) - mu * mu + 1e-5f);
        }
        __syncthreads();
        hb2[tid] = (val2 - stat[0]) * stat[1] * ln2g[tid] + ln2b[tid];
        __syncthreads();
    }

    __shared__ float th[64];
    if (tid < 64) {
        float a = b1[tid];
        for (int dd = 0; dd < D; dd++) a = fmaf(hb2[dd], w1[dd * 64 + tid], a);
        th[tid] = fmaxf(a, 0.0f) * w2[tid];
    }
    __syncthreads();
    if (tid < 32) {
        float s = th[tid] + th[tid + 32];
        #pragma unroll
        for (int o = 16; o; o >>= 1) s += __shfl_xor_sync(0xffffffffu, s, o);
        if (tid == 0) out[b] = s + b2[0];
    }
}

// ===================================================================================
extern "C" void kernel_launch(void* const* d_in, const int* in_sizes, int n_in,
                              void* d_out, int out_size)
{
    const float* x     = (const float*)d_in[0];
    const int*   idx   = (const int*)  d_in[1];
    const float* w_in  = (const float*)d_in[2];
    const float* b_in  = (const float*)d_in[3];
    const float* wq    = (const float*)d_in[4];
    const float* bq    = (const float*)d_in[5];
    const float* wk    = (const float*)d_in[6];
    const float* bk    = (const float*)d_in[7];
    const float* wv    = (const float*)d_in[8];
    const float* bv    = (const float*)d_in[9];
    const float* wo    = (const float*)d_in[10];
    const float* bo    = (const float*)d_in[11];
    const float* w_ff1 = (const float*)d_in[12];
    const float* b_ff1 = (const float*)d_in[13];
    const float* w_ff2 = (const float*)d_in[14];
    const float* b_ff2 = (const float*)d_in[15];
    const float* ln1_g = (const float*)d_in[16];
    const float* ln1_b = (const float*)d_in[17];
    const float* ln2_g = (const float*)d_in[18];
    const float* ln2_b = (const float*)d_in[19];
    const float* w_fc1 = (const float*)d_in[20];
    const float* b_fc1 = (const float*)d_in[21];
    const float* w_fc2 = (const float*)d_in[22];
    const float* b_fc2 = (const float*)d_in[23];
    float* out = (float*)d_out;

    float *h, *q, *k, *v, *nx, *Mv, *vm, *ctxl, *am, *al, *av; int *top, *member;
    __nv_bfloat16 *xhi, *xlo, *hhi, *hlo, *chi, *clo, *fhi, *flo, *whi, *wlo;
    cudaGetSymbolAddress((void**)&h,   g_h);
    cudaGetSymbolAddress((void**)&q,   g_q);
    cudaGetSymbolAddress((void**)&k,   g_k);
    cudaGetSymbolAddress((void**)&v,   g_v);
    cudaGetSymbolAddress((void**)&nx,  g_nx);
    cudaGetSymbolAddress((void**)&Mv,  g_M);
    cudaGetSymbolAddress((void**)&top, g_top);
    cudaGetSymbolAddress((void**)&member, g_member);
    cudaGetSymbolAddress((void**)&vm,  g_vm);
    cudaGetSymbolAddress((void**)&ctxl, g_ctxl);
    cudaGetSymbolAddress((void**)&am,  g_am);
    cudaGetSymbolAddress((void**)&al,  g_al);
    cudaGetSymbolAddress((void**)&av,  g_av);
    cudaGetSymbolAddress((void**)&xhi, g_x_hi);  cudaGetSymbolAddress((void**)&xlo, g_x_lo);
    cudaGetSymbolAddress((void**)&hhi, g_h_hi);  cudaGetSymbolAddress((void**)&hlo, g_h_lo);
    cudaGetSymbolAddress((void**)&chi, g_ctx_hi); cudaGetSymbolAddress((void**)&clo, g_ctx_lo);
    cudaGetSymbolAddress((void**)&fhi, g_ff_hi); cudaGetSymbolAddress((void**)&flo, g_ff_lo);
    cudaGetSymbolAddress((void**)&whi, g_wt_hi); cudaGetSymbolAddress((void**)&wlo, g_wt_lo);

    cudaFuncSetAttribute(mma_gemm_bf16, cudaFuncAttributeMaxDynamicSharedMemorySize, GEMM_SMEM_V4);

    const int Mrows = B_ * L_;
    dim3 gD  (D / 128,   Mrows / 128);
    dim3 gQKV(3 * D / 128, Mrows / 128);
    dim3 gFF (DFF / 128, Mrows / 128);
    dim3 tb(32, 8);

    const size_t o_in = 0;
    auto o_q  = [&](int l){ return (size_t)FIN * D + (size_t)l * LYR_SZ; };
    auto o_o  = [&](int l){ return o_q(l) + 196608; };
    auto o_f1 = [&](int l){ return o_q(l) + 262144; };
    auto o_f2 = [&](int l){ return o_q(l) + 524288; };

    split_kernel<<<(B_ * L_ * FIN) / 512, 256>>>(x, xhi, xlo, B_ * L_ * FIN);
    transpose_all_kernel<<<1544, tb>>>(w_in, wq, wk, wv, wo, w_ff1, w_ff2, whi, wlo);
    mma_gemm_bf16<<<gD, 256, GEMM_SMEM_V4>>>(xhi, xlo, whi + o_in, wlo + o_in,
        b_in, nullptr, nullptr, h, nullptr, nullptr, hhi, hlo, nullptr, Mrows, D, FIN, 0, 3, 0);

    // ---------------- layer 0 (full) ----------------
    {
        const int layer = 0;
        const int* ixL = idx;

        mma_gemm_bf16<<<gQKV, 256, GEMM_SMEM_V4>>>(hhi, hlo, whi + o_q(layer), wlo + o_q(layer),
            bq, bk, bv, q, k, v, nullptr, nullptr, nullptr, Mrows, 768, D, 0, 1, 1);

        qkvm_kernel<<<QK_BLOCKS + B_ * H_, 256>>>(q, k, ixL, Mv, v, vm);
        topk_kernel<<<B_ * H_, 256>>>(Mv, top);
        ctxfill_kernel<<<(B_ * L_ * D) / 1024, 256>>>(vm, chi, clo);
        attn_part_kernel<<<B_ * H_ * 4, 256>>>(q, k, v, top, am, al, av);
        attn_combine_kernel<<<B_ * H_, 256>>>(top, am, al, av, chi, clo);

        mma_gemm_bf16<<<gD, 256, GEMM_SMEM_V4>>>(chi, clo, whi + o_o(layer), wlo + o_o(layer),
            bo, nullptr, nullptr, nx, nullptr, nullptr, nullptr, nullptr, h,
            Mrows, D, D, 0, 1, 0);
        add_ln_kernel<<<Mrows / 2, 256>>>(nx, ln1_g, ln1_b, h, hhi, hlo);

        mma_gemm_bf16<<<gFF, 256, GEMM_SMEM_V4>>>(hhi, hlo, whi + o_f1(layer), wlo + o_f1(layer),
            b_ff1, nullptr, nullptr, nullptr, nullptr, nullptr, fhi, flo, nullptr,
            Mrows, DFF, D, 1, 2, 0);
        mma_gemm_bf16<<<gD, 256, GEMM_SMEM_V4>>>(fhi, flo, whi + o_f2(layer), wlo + o_f2(layer),
            b_ff2, nullptr, nullptr, nx, nullptr, nullptr, nullptr, nullptr, h,
            Mrows, D, DFF, 0, 1, 0);
        add_ln_kernel<<<Mrows / 2, 256>>>(nx, ln2_g, ln2_b, h, hhi, hlo);
    }

    // ---------------- layer 1 (output-funnel pruned, membership test) ----------------
    {
        const int layer = 1;
        const int* ixL = idx + (size_t)L_ * S_;

        mma_gemm_bf16<<<gQKV, 256, GEMM_SMEM_V4>>>(hhi, hlo, whi + o_q(layer), wlo + o_q(layer),
            bq + D, bk + D, bv + D, q, k, v, nullptr, nullptr, nullptr, Mrows, 768, D, 0, 1, 1);

        qkvm_kernel<<<QK_BLOCKS + B_ * H_, 256>>>(q, k, ixL, Mv, v, vm);
        member_kernel<<<B_ * H_, 256>>>(Mv, member);
        last_attn_kernel<<<B_ * H_, 256>>>(q, k, v, member, vm, ctxl);

        final_head_kernel<<<B_, 256>>>(h, ctxl,
            wo + (size_t)D * D, bo + D,
            ln1_g + D, ln1_b + D,
            w_ff1 + (size_t)D * DFF, b_ff1 + DFF,
            w_ff2 + (size_t)DFF * D, b_ff2 + D,
            ln2_g + D, ln2_b + D,
            w_fc1, b_fc1, w_fc2, b_fc2, out);
    }
}